// round 1
// baseline (speedup 1.0000x reference)
#include <cuda_runtime.h>

#define C   32
#define HF  96
#define WF  192
#define DD  192
#define HOUT 384
#define WOUT 768
#define ND  48
#define CHW (HF*WF)
#define COST_ELEMS (DD*HF*WF)

// ---------------------------------------------------------------------------
// Kernel 1: normalized cosine cost volume.
// grid (96 h, 2 d-chunks), 192 threads. Per block: load one h-row of both
// feature maps into smem, L2-normalize per pixel over C, then compute a
// 96d x 192w triangular correlation tile with TD=8 x TW=2 register tiles.
// cost[d,h,w] = sum_c rn[c,w]*tn[c,w-d], exactly 0 for w<d.
// ---------------------------------------------------------------------------
__global__ __launch_bounds__(192) void cost_kernel(
    const float* __restrict__ ref, const float* __restrict__ tgt,
    float* __restrict__ out)
{
    __shared__ float r[C][WF];
    __shared__ float t[C][WF];
    const int h   = blockIdx.x;
    const int tid = threadIdx.x;   // 0..191 == w

    // load: c = i, w = tid (blockDim == WF)
    #pragma unroll
    for (int c = 0; c < C; c++) {
        r[c][tid] = ref[c*CHW + h*WF + tid];
        t[c][tid] = tgt[c*CHW + h*WF + tid];
    }
    __syncthreads();

    // per-pixel channel normalization (thread owns column w = tid)
    {
        float sr = 0.f, st = 0.f;
        #pragma unroll
        for (int c = 0; c < C; c++) {
            float a = r[c][tid]; sr = fmaf(a, a, sr);
            float b = t[c][tid]; st = fmaf(b, b, st);
        }
        float ir = rsqrtf(sr + 1e-12f);
        float it = rsqrtf(st + 1e-12f);
        #pragma unroll
        for (int c = 0; c < C; c++) { r[c][tid] *= ir; t[c][tid] *= it; }
    }
    __syncthreads();

    const int dbase = blockIdx.y * 96;

    #pragma unroll
    for (int it = 0; it < 6; it++) {
        int tile = tid + it*192;          // 0..1151  (96 wpairs x 12 d-octs)
        int w0 = (tile % 96) * 2;
        int d0 = dbase + (tile / 96) * 8;

        float acc0[8], acc1[8];
        #pragma unroll
        for (int i = 0; i < 8; i++) { acc0[i] = 0.f; acc1[i] = 0.f; }

        const int bb = w0 - d0 - 7;       // b[j] = t[c][bb+j], j=0..8
        if (w0 + 1 >= d0) {               // tile has at least one valid output
            if (bb >= 0) {                // fully in-range fast path
                #pragma unroll
                for (int c = 0; c < C; c++) {
                    float a0 = r[c][w0], a1 = r[c][w0+1];
                    float b[9];
                    #pragma unroll
                    for (int j = 0; j < 9; j++) b[j] = t[c][bb + j];
                    #pragma unroll
                    for (int i = 0; i < 8; i++) {
                        acc0[i] = fmaf(a0, b[7 - i], acc0[i]);  // w=w0,   d=d0+i
                        acc1[i] = fmaf(a1, b[8 - i], acc1[i]);  // w=w0+1, d=d0+i
                    }
                }
            } else {                      // partially valid: OOB -> 0 (exact)
                #pragma unroll
                for (int c = 0; c < C; c++) {
                    float a0 = r[c][w0], a1 = r[c][w0+1];
                    float b[9];
                    #pragma unroll
                    for (int j = 0; j < 9; j++) {
                        int ix = bb + j;
                        b[j] = (ix >= 0) ? t[c][ix] : 0.f;
                    }
                    #pragma unroll
                    for (int i = 0; i < 8; i++) {
                        acc0[i] = fmaf(a0, b[7 - i], acc0[i]);
                        acc1[i] = fmaf(a1, b[8 - i], acc1[i]);
                    }
                }
            }
        }
        #pragma unroll
        for (int i = 0; i < 8; i++) {
            int d = d0 + i;
            float2 v = make_float2(acc0[i], acc1[i]);
            *reinterpret_cast<float2*>(&out[(d*HF + h)*WF + w0]) = v;
        }
    }
}

// ---------------------------------------------------------------------------
// Kernel 2: fused trilinear upsample (x4 in d,h,w; jax half-pixel + edge
// renorm == clamped lerp) + argmax over 192 d-samples + clamp(.,1).
// Piecewise-linear reduction: segment-sample maxima reduce to per-grid-point
// candidates 0.875*s[e] + 0.125*max(s[e-1], s[e+1]) plus exact edge samples
// s[0] (k=0) and s[47] (k=190). First-occurrence ties preserved.
// Block = 32x8 output pixels; shared tile of 4x10 corner columns x 48 d.
// ---------------------------------------------------------------------------
__device__ __forceinline__ float bilin1(const float* c00, const float* c01,
                                        const float* c10, const float* c11,
                                        int d, float fw, float fh)
{
    float t0 = fmaf(fw, c01[d] - c00[d], c00[d]);
    float t1 = fmaf(fw, c11[d] - c10[d], c10[d]);
    return fmaf(fh, t1 - t0, t0);
}

__global__ __launch_bounds__(256) void pred_kernel(
    const float* __restrict__ cost, float* __restrict__ pred)
{
    __shared__ float sc[4][10][ND];    // [h-row][w-col][d], d contiguous
    const int tx = threadIdx.x, ty = threadIdx.y;
    const int tid = ty*32 + tx;
    const int hb = 2*(int)blockIdx.y - 1;
    const int wb = 8*(int)blockIdx.x - 1;

    for (int i = tid; i < 4*10*ND; i += 256) {
        int wc = i % 10;
        int hr = (i / 10) % 4;
        int d  = i / 40;
        int hh = min(max(hb + hr, 0), HF - 1);
        int ww = min(max(wb + wc, 0), WF - 1);
        sc[hr][wc][d] = cost[(d*HF + hh)*WF + ww];
    }
    __syncthreads();

    const int wo = blockIdx.x*32 + tx;
    const int ho = blockIdx.y*8 + ty;

    float xh = fminf(fmaxf(0.25f*(float)ho - 0.375f, 0.f), (float)(HF - 1));
    int   h0 = min((int)xh, HF - 2);
    float fh = xh - (float)h0;
    float xw = fminf(fmaxf(0.25f*(float)wo - 0.375f, 0.f), (float)(WF - 1));
    int   w0 = min((int)xw, WF - 2);
    float fw = xw - (float)w0;

    const int lh = h0 - hb;
    const int lw = w0 - wb;
    const float* c00 = sc[lh][lw];
    const float* c01 = sc[lh][lw+1];
    const float* c10 = sc[lh+1][lw];
    const float* c11 = sc[lh+1][lw+1];

    // s[d]: spatially-interpolated cost at the 48 coarse disparity levels
    float s[ND];
    #pragma unroll
    for (int q = 0; q < ND/4; q++) {
        float4 v00 = *reinterpret_cast<const float4*>(c00 + q*4);
        float4 v01 = *reinterpret_cast<const float4*>(c01 + q*4);
        float4 v10 = *reinterpret_cast<const float4*>(c10 + q*4);
        float4 v11 = *reinterpret_cast<const float4*>(c11 + q*4);
        {
            float t0 = fmaf(fw, v01.x - v00.x, v00.x);
            float t1 = fmaf(fw, v11.x - v10.x, v10.x);
            s[q*4+0] = fmaf(fh, t1 - t0, t0);
        }
        {
            float t0 = fmaf(fw, v01.y - v00.y, v00.y);
            float t1 = fmaf(fw, v11.y - v10.y, v10.y);
            s[q*4+1] = fmaf(fh, t1 - t0, t0);
        }
        {
            float t0 = fmaf(fw, v01.z - v00.z, v00.z);
            float t1 = fmaf(fw, v11.z - v10.z, v10.z);
            s[q*4+2] = fmaf(fh, t1 - t0, t0);
        }
        {
            float t0 = fmaf(fw, v01.w - v00.w, v00.w);
            float t1 = fmaf(fw, v11.w - v10.w, v10.w);
            s[q*4+3] = fmaf(fh, t1 - t0, t0);
        }
    }

    // argmax over the 192 upsampled samples via candidate reduction.
    // k=0,1 give exactly s[0]; k=190,191 give exactly s[47]; interior samples
    // reduce to per-e candidates at k=4e+1 (left nbr) / 4e+2 (right nbr).
    float best = s[0];
    int bestE = -1;                         // -1 => k = 0
    #pragma unroll
    for (int e = 0; e < ND; e++) {
        float nb = (e == 0)      ? s[1]
                 : (e == ND - 1) ? s[ND - 2]
                                 : fmaxf(s[e-1], s[e+1]);
        float cand = fmaf(0.875f, s[e], 0.125f * nb);
        if (cand > best) { best = cand; bestE = e; }
    }

    int k;
    if (s[ND-1] > best) {
        k = 4*(ND-1) + 2;                   // 190
    } else if (bestE < 0) {
        k = 0;
    } else {
        float sm1 = -3.0e38f, sp1 = -3.0e38f;
        if (bestE > 0)      sm1 = bilin1(c00, c01, c10, c11, bestE - 1, fw, fh);
        if (bestE < ND - 1) sp1 = bilin1(c00, c01, c10, c11, bestE + 1, fw, fh);
        k = 4*bestE + 1 + ((sp1 > sm1) ? 1 : 0);   // tie -> left (smaller k)
    }
    k = max(k, 1);
    pred[ho*WOUT + wo] = (float)k;
}

// ---------------------------------------------------------------------------
extern "C" void kernel_launch(void* const* d_in, const int* in_sizes, int n_in,
                              void* d_out, int out_size)
{
    const float* left  = (const float*)d_in[0];
    const float* right = (const float*)d_in[1];
    float* out = (float*)d_out;

    dim3 g1(HF, 2), b1(192);
    cost_kernel<<<g1, b1>>>(left, right, out);

    dim3 g2(WOUT/32, HOUT/8), b2(32, 8);
    pred_kernel<<<g2, b2>>>(out, out + COST_ELEMS);
}

// round 2
// speedup vs baseline: 1.5910x; 1.5910x over previous
#include <cuda_runtime.h>

#define C   32
#define HF  96
#define WF  192
#define DD  192
#define HOUT 384
#define WOUT 768
#define ND  48
#define CHW (HF*WF)
#define COST_ELEMS (DD*HF*WF)

// ---------------------------------------------------------------------------
// Kernel 1: normalized cosine cost volume.
// grid (96 h, 2 d-interleave), 288 threads. Per block: load one h-row of both
// feature maps into smem (float4), L2-normalize per pixel over C, then compute
// 4w x 8d register tiles with vectorized LDS.128 operand loads.
// cost[d,h,w] = sum_c rn[c,w]*tn[c,w-d], exactly 0 for w<d.
// Block y takes d-octs {y, y+2, y+4, ...} (interleaved to balance the
// triangular valid region between the two blocks per h).
// ---------------------------------------------------------------------------
__global__ __launch_bounds__(288) void cost_kernel(
    const float* __restrict__ ref, const float* __restrict__ tgt,
    float* __restrict__ out)
{
    __shared__ float r[C][WF];
    __shared__ float t[C][WF];
    const int h   = blockIdx.x;
    const int tid = threadIdx.x;   // 0..287

    // vectorized load of both rows: 2 x 32 x 192 floats = 2 x 1536 float4
    {
        float4* r4 = reinterpret_cast<float4*>(&r[0][0]);
        float4* t4 = reinterpret_cast<float4*>(&t[0][0]);
        #pragma unroll
        for (int it = 0; it < 6; it++) {
            int i = tid + it * 288;
            if (i < C * (WF / 4)) {
                int c = i / (WF / 4);
                int k = i % (WF / 4);
                r4[c * (WF / 4) + k] =
                    *reinterpret_cast<const float4*>(ref + c*CHW + h*WF + k*4);
                t4[c * (WF / 4) + k] =
                    *reinterpret_cast<const float4*>(tgt + c*CHW + h*WF + k*4);
            }
        }
    }
    __syncthreads();

    // per-pixel channel normalization (threads 0..191 own column w = tid)
    if (tid < WF) {
        float sr = 0.f, st = 0.f;
        #pragma unroll
        for (int c = 0; c < C; c++) {
            float a = r[c][tid]; sr = fmaf(a, a, sr);
            float b = t[c][tid]; st = fmaf(b, b, st);
        }
        float ir = rsqrtf(sr + 1e-12f);
        float itv = rsqrtf(st + 1e-12f);
        #pragma unroll
        for (int c = 0; c < C; c++) { r[c][tid] *= ir; t[c][tid] *= itv; }
    }
    __syncthreads();

    const int by = blockIdx.y;

    #pragma unroll
    for (int it = 0; it < 2; it++) {
        const int tau = tid + it * 288;          // 0..575
        const int wq  = tau % 48;                // w-quad
        const int dq  = tau / 48;                // 0..11 local d-oct
        const int w0  = wq * 4;
        const int d0  = 8 * (2 * dq + by);       // interleaved d-oct

        float4 acc[8];
        #pragma unroll
        for (int i = 0; i < 8; i++) acc[i] = make_float4(0.f, 0.f, 0.f, 0.f);

        const int bb  = w0 - d0 - 7;             // t window: bb .. bb+10
        const int bb1 = bb - 1;                  // aligned vec base (bb1 % 4 == 0)

        if (bb >= 1) {
            // fully in-range fast path: all vector loads valid
            #pragma unroll
            for (int c = 0; c < C; c++) {
                float4 a  = *reinterpret_cast<const float4*>(&r[c][w0]);
                float4 v0 = *reinterpret_cast<const float4*>(&t[c][bb1]);
                float4 v1 = *reinterpret_cast<const float4*>(&t[c][bb1 + 4]);
                float4 v2 = *reinterpret_cast<const float4*>(&t[c][bb1 + 8]);
                float e[12] = {v0.x, v0.y, v0.z, v0.w,
                               v1.x, v1.y, v1.z, v1.w,
                               v2.x, v2.y, v2.z, v2.w};
                #pragma unroll
                for (int i = 0; i < 8; i++) {
                    acc[i].x = fmaf(a.x, e[8  - i], acc[i].x);  // w=w0,   d=d0+i
                    acc[i].y = fmaf(a.y, e[9  - i], acc[i].y);  // w=w0+1
                    acc[i].z = fmaf(a.z, e[10 - i], acc[i].z);  // w=w0+2
                    acc[i].w = fmaf(a.w, e[11 - i], acc[i].w);  // w=w0+3
                }
            }
        } else if (bb >= -10) {
            // partially valid edge tile: guarded scalar loads, OOB -> 0 (exact)
            #pragma unroll
            for (int c = 0; c < C; c++) {
                float4 a = *reinterpret_cast<const float4*>(&r[c][w0]);
                float e[12];
                #pragma unroll
                for (int j = 0; j < 12; j++) {
                    int ix = bb1 + j;
                    e[j] = (ix >= 0) ? t[c][ix] : 0.f;
                }
                #pragma unroll
                for (int i = 0; i < 8; i++) {
                    acc[i].x = fmaf(a.x, e[8  - i], acc[i].x);
                    acc[i].y = fmaf(a.y, e[9  - i], acc[i].y);
                    acc[i].z = fmaf(a.z, e[10 - i], acc[i].z);
                    acc[i].w = fmaf(a.w, e[11 - i], acc[i].w);
                }
            }
        }
        // bb < -10: entire tile is w < d -> exact zeros (acc already 0)

        #pragma unroll
        for (int i = 0; i < 8; i++) {
            *reinterpret_cast<float4*>(&out[((d0 + i)*HF + h)*WF + w0]) = acc[i];
        }
    }
}

// ---------------------------------------------------------------------------
// Kernel 2: fused trilinear upsample (x4 in d,h,w; jax half-pixel + edge
// renorm == clamped lerp) + argmax over 192 d-samples + clamp(.,1).
// Streaming 3-value window over the 48 coarse-d interpolated values:
// candidate at e = 0.875*s[e] + 0.125*max(s[e-1], s[e+1]); exact edge
// samples s[0] (k=0) and s[47] (k=190). First-occurrence ties preserved.
// smem tile padded to stride 49 -> bank-conflict-free (lw*17 mod 32 distinct).
// ---------------------------------------------------------------------------
__device__ __forceinline__ float bilin1(const float* __restrict__ c00,
                                        const float* __restrict__ c01,
                                        const float* __restrict__ c10,
                                        const float* __restrict__ c11,
                                        int d, float fw, float fh)
{
    float t0 = fmaf(fw, c01[d] - c00[d], c00[d]);
    float t1 = fmaf(fw, c11[d] - c10[d], c10[d]);
    return fmaf(fh, t1 - t0, t0);
}

__global__ __launch_bounds__(256) void pred_kernel(
    const float* __restrict__ cost, float* __restrict__ pred)
{
    __shared__ float sc[4][10][49];    // [h-row][w-col][d], padded stride
    const int tx = threadIdx.x, ty = threadIdx.y;
    const int tid = ty*32 + tx;
    const int hb = 2*(int)blockIdx.y - 1;
    const int wb = 8*(int)blockIdx.x - 1;

    #pragma unroll
    for (int it = 0; it < 8; it++) {
        int i = tid + it * 256;
        if (i < 4*10*ND) {
            int wc = i % 10;
            int hr = (i / 10) % 4;
            int d  = i / 40;
            int hh = min(max(hb + hr, 0), HF - 1);
            int ww = min(max(wb + wc, 0), WF - 1);
            sc[hr][wc][d] = cost[(d*HF + hh)*WF + ww];
        }
    }
    __syncthreads();

    const int wo = blockIdx.x*32 + tx;
    const int ho = blockIdx.y*8 + ty;

    float xh = fminf(fmaxf(0.25f*(float)ho - 0.375f, 0.f), (float)(HF - 1));
    int   h0 = min((int)xh, HF - 2);
    float fh = xh - (float)h0;
    float xw = fminf(fmaxf(0.25f*(float)wo - 0.375f, 0.f), (float)(WF - 1));
    int   w0 = min((int)xw, WF - 2);
    float fw = xw - (float)w0;

    const int lh = h0 - hb;
    const int lw = w0 - wb;
    const float* c00 = sc[lh][lw];
    const float* c01 = sc[lh][lw+1];
    const float* c10 = sc[lh+1][lw];
    const float* c11 = sc[lh+1][lw+1];

    // streaming argmax over candidate reductions (window of 3 s-values)
    float sm1  = 0.f;
    float scur = bilin1(c00, c01, c10, c11, 0, fw, fh);
    float snx  = bilin1(c00, c01, c10, c11, 1, fw, fh);
    float best = scur;                 // exact sample s[0] at k = 0
    int bestE  = -1;                   // -1 => k = 0
    float s47  = 0.f;

    #pragma unroll
    for (int e = 0; e < ND; e++) {
        float nb = (e == 0)      ? snx
                 : (e == ND - 1) ? sm1
                                 : fmaxf(sm1, snx);
        float cand = fmaf(0.875f, scur, 0.125f * nb);
        if (cand > best) { best = cand; bestE = e; }
        if (e == ND - 1) s47 = scur;
        sm1 = scur;
        scur = snx;
        if (e + 2 < ND) snx = bilin1(c00, c01, c10, c11, e + 2, fw, fh);
    }

    int k;
    if (s47 > best) {
        k = 4*(ND-1) + 2;                   // 190: exact sample s[47]
    } else if (bestE < 0) {
        k = 0;
    } else {
        float smL = -3.0e38f, smR = -3.0e38f;
        if (bestE > 0)      smL = bilin1(c00, c01, c10, c11, bestE - 1, fw, fh);
        if (bestE < ND - 1) smR = bilin1(c00, c01, c10, c11, bestE + 1, fw, fh);
        k = 4*bestE + 1 + ((smR > smL) ? 1 : 0);   // tie -> left (smaller k)
    }
    k = max(k, 1);
    pred[ho*WOUT + wo] = (float)k;
}

// ---------------------------------------------------------------------------
extern "C" void kernel_launch(void* const* d_in, const int* in_sizes, int n_in,
                              void* d_out, int out_size)
{
    const float* left  = (const float*)d_in[0];
    const float* right = (const float*)d_in[1];
    float* out = (float*)d_out;

    dim3 g1(HF, 2), b1(288);
    cost_kernel<<<g1, b1>>>(left, right, out);

    dim3 g2(WOUT/32, HOUT/8), b2(32, 8);
    pred_kernel<<<g2, b2>>>(out, out + COST_ELEMS);
}

// round 3
// speedup vs baseline: 2.0515x; 1.2895x over previous
#include <cuda_runtime.h>

#define C   32
#define HF  96
#define WF  192
#define DD  192
#define HOUT 384
#define WOUT 768
#define ND  48
#define CHW (HF*WF)
#define COST_ELEMS (DD*HF*WF)

// ---------------------------------------------------------------------------
// Kernel 1: normalized cosine cost volume. ONE WAVE: grid (48 h-pairs, 3),
// 768 threads, 96KB dynamic smem (1 block/SM, 24 warps). Block loads 2 h-rows
// of both feature maps, L2-normalizes per pixel, then each thread computes
// exactly one 4w x 8d register tile with LDS.128 operand loads.
// cost[d,h,w] = sum_c rn[c,w]*tn[c,w-d], exactly 0 for w<d.
// blockIdx.y takes d-octs {y, y+3, y+6, ...} (interleave balances triangle).
// ---------------------------------------------------------------------------
__global__ __launch_bounds__(768) void cost_kernel(
    const float* __restrict__ ref, const float* __restrict__ tgt,
    float* __restrict__ out)
{
    extern __shared__ float sm[];
    // layout: r[2][C][WF] then t[2][C][WF]
    float (*r)[C][WF] = reinterpret_cast<float (*)[C][WF]>(sm);
    float (*t)[C][WF] = reinterpret_cast<float (*)[C][WF]>(sm + 2*C*WF);

    const int hp  = blockIdx.x;          // h-pair 0..47
    const int by  = blockIdx.y;          // 0..2
    const int tid = threadIdx.x;         // 0..767
    const int hrow0 = hp * 2;

    // vectorized loads: 4 plane-rows x 1536 float4 each
    {
        const float* srcs[4] = { ref + hrow0*WF, ref + (hrow0+1)*WF,
                                 tgt + hrow0*WF, tgt + (hrow0+1)*WF };
        float* dsts[4] = { &r[0][0][0], &r[1][0][0], &t[0][0][0], &t[1][0][0] };
        #pragma unroll
        for (int p = 0; p < 4; p++) {
            #pragma unroll
            for (int j = 0; j < 2; j++) {
                int k  = tid + j*768;          // 0..1535
                int c  = k / 48;
                int kk = k % 48;
                reinterpret_cast<float4*>(dsts[p])[k] =
                    *reinterpret_cast<const float4*>(srcs[p] + c*CHW + kk*4);
            }
        }
    }
    __syncthreads();

    // per-pixel channel normalization: 384 columns (2 rows x 192 w)
    if (tid < 2*WF) {
        int row = tid / WF;
        int w   = tid % WF;
        float sr = 0.f, st = 0.f;
        #pragma unroll
        for (int c = 0; c < C; c++) {
            float a = r[row][c][w]; sr = fmaf(a, a, sr);
            float b = t[row][c][w]; st = fmaf(b, b, st);
        }
        float ir  = rsqrtf(sr + 1e-12f);
        float itv = rsqrtf(st + 1e-12f);
        #pragma unroll
        for (int c = 0; c < C; c++) { r[row][c][w] *= ir; t[row][c][w] *= itv; }
    }
    __syncthreads();

    // one tile per thread
    const int hr = (tid >= 384) ? 1 : 0;
    const int tm = tid - hr*384;         // 0..383
    const int wq = tm % 48;
    const int dq = tm / 48;              // 0..7
    const int w0 = wq * 4;
    const int d0 = 8 * (3*dq + by);      // interleaved d-oct
    const int h  = hrow0 + hr;

    float4 acc[8];
    #pragma unroll
    for (int i = 0; i < 8; i++) acc[i] = make_float4(0.f, 0.f, 0.f, 0.f);

    const int bb  = w0 - d0 - 7;         // t window: bb .. bb+10
    const int bb1 = bb - 1;              // aligned vec base (bb1 % 4 == 0)

    if (bb >= 1) {
        // fully in-range fast path: all vector loads valid
        #pragma unroll
        for (int c = 0; c < C; c++) {
            float4 a  = *reinterpret_cast<const float4*>(&r[hr][c][w0]);
            float4 v0 = *reinterpret_cast<const float4*>(&t[hr][c][bb1]);
            float4 v1 = *reinterpret_cast<const float4*>(&t[hr][c][bb1 + 4]);
            float4 v2 = *reinterpret_cast<const float4*>(&t[hr][c][bb1 + 8]);
            float e[12] = {v0.x, v0.y, v0.z, v0.w,
                           v1.x, v1.y, v1.z, v1.w,
                           v2.x, v2.y, v2.z, v2.w};
            #pragma unroll
            for (int i = 0; i < 8; i++) {
                acc[i].x = fmaf(a.x, e[8  - i], acc[i].x);  // w=w0,   d=d0+i
                acc[i].y = fmaf(a.y, e[9  - i], acc[i].y);  // w=w0+1
                acc[i].z = fmaf(a.z, e[10 - i], acc[i].z);  // w=w0+2
                acc[i].w = fmaf(a.w, e[11 - i], acc[i].w);  // w=w0+3
            }
        }
    } else if (bb >= -10) {
        // partially valid edge tile: guarded scalar loads, OOB -> 0 (exact)
        #pragma unroll
        for (int c = 0; c < C; c++) {
            float4 a = *reinterpret_cast<const float4*>(&r[hr][c][w0]);
            float e[12];
            #pragma unroll
            for (int j = 0; j < 12; j++) {
                int ix = bb1 + j;
                e[j] = (ix >= 0) ? t[hr][c][ix] : 0.f;
            }
            #pragma unroll
            for (int i = 0; i < 8; i++) {
                acc[i].x = fmaf(a.x, e[8  - i], acc[i].x);
                acc[i].y = fmaf(a.y, e[9  - i], acc[i].y);
                acc[i].z = fmaf(a.z, e[10 - i], acc[i].z);
                acc[i].w = fmaf(a.w, e[11 - i], acc[i].w);
            }
        }
    }
    // bb < -10: entire tile is w < d -> exact zeros

    #pragma unroll
    for (int i = 0; i < 8; i++) {
        *reinterpret_cast<float4*>(&out[((d0 + i)*HF + h)*WF + w0]) = acc[i];
    }
}

// ---------------------------------------------------------------------------
// Kernel 2: fused trilinear upsample (jax half-pixel == clamped lerp) +
// argmax over 192 d-samples + clamp(.,1). Chunked-by-8 vectorized streaming:
// candidate at e = 0.875*s[e] + 0.125*max(s[e-1], s[e+1]); exact edge
// samples s[0] (k=0) and s[47] (k=190). First-occurrence ties preserved
// (ascending e, strict >). smem stride 52: 16B-aligned, conflict-free phases.
// ---------------------------------------------------------------------------
#define SSTR 52

__device__ __forceinline__ float bilin1(const float* __restrict__ c00,
                                        const float* __restrict__ c01,
                                        const float* __restrict__ c10,
                                        const float* __restrict__ c11,
                                        int d, float fw, float fh)
{
    float t0 = fmaf(fw, c01[d] - c00[d], c00[d]);
    float t1 = fmaf(fw, c11[d] - c10[d], c10[d]);
    return fmaf(fh, t1 - t0, t0);
}

__device__ __forceinline__ void chunk8(const float* __restrict__ c00,
                                       const float* __restrict__ c01,
                                       const float* __restrict__ c10,
                                       const float* __restrict__ c11,
                                       int dbase, float fw, float fh,
                                       float* __restrict__ s)
{
    #pragma unroll
    for (int half = 0; half < 2; half++) {
        float4 v00 = *reinterpret_cast<const float4*>(c00 + dbase + half*4);
        float4 v01 = *reinterpret_cast<const float4*>(c01 + dbase + half*4);
        float4 v10 = *reinterpret_cast<const float4*>(c10 + dbase + half*4);
        float4 v11 = *reinterpret_cast<const float4*>(c11 + dbase + half*4);
        float t0, t1;
        t0 = fmaf(fw, v01.x - v00.x, v00.x);
        t1 = fmaf(fw, v11.x - v10.x, v10.x);
        s[half*4+0] = fmaf(fh, t1 - t0, t0);
        t0 = fmaf(fw, v01.y - v00.y, v00.y);
        t1 = fmaf(fw, v11.y - v10.y, v10.y);
        s[half*4+1] = fmaf(fh, t1 - t0, t0);
        t0 = fmaf(fw, v01.z - v00.z, v00.z);
        t1 = fmaf(fw, v11.z - v10.z, v10.z);
        s[half*4+2] = fmaf(fh, t1 - t0, t0);
        t0 = fmaf(fw, v01.w - v00.w, v00.w);
        t1 = fmaf(fw, v11.w - v10.w, v10.w);
        s[half*4+3] = fmaf(fh, t1 - t0, t0);
    }
}

__global__ __launch_bounds__(256) void pred_kernel(
    const float* __restrict__ cost, float* __restrict__ pred)
{
    __shared__ float sc[4][10][SSTR];  // [h-row][w-col][d], padded stride
    const int tx = threadIdx.x, ty = threadIdx.y;
    const int tid = ty*32 + tx;
    const int hb = 2*(int)blockIdx.y - 1;
    const int wb = 8*(int)blockIdx.x - 1;

    #pragma unroll
    for (int it = 0; it < 8; it++) {
        int i = tid + it * 256;
        if (i < 4*10*ND) {
            int wc = i % 10;
            int hr = (i / 10) % 4;
            int d  = i / 40;
            int hh = min(max(hb + hr, 0), HF - 1);
            int ww = min(max(wb + wc, 0), WF - 1);
            sc[hr][wc][d] = cost[(d*HF + hh)*WF + ww];
        }
    }
    __syncthreads();

    const int wo = blockIdx.x*32 + tx;
    const int ho = blockIdx.y*8 + ty;

    float xh = fminf(fmaxf(0.25f*(float)ho - 0.375f, 0.f), (float)(HF - 1));
    int   h0 = min((int)xh, HF - 2);
    float fh = xh - (float)h0;
    float xw = fminf(fmaxf(0.25f*(float)wo - 0.375f, 0.f), (float)(WF - 1));
    int   w0 = min((int)xw, WF - 2);
    float fw = xw - (float)w0;

    const int lh = h0 - hb;
    const int lw = w0 - wb;
    const float* c00 = &sc[lh][lw][0];
    const float* c01 = &sc[lh][lw+1][0];
    const float* c10 = &sc[lh+1][lw][0];
    const float* c11 = &sc[lh+1][lw+1][0];

    float sA[8], sB[8];
    chunk8(c00, c01, c10, c11, 0, fw, fh, sA);

    float best = sA[0];                  // exact sample s[0] at k = 0
    int bestE = -1;                      // -1 => k = 0

    // e = 0..6 (within chunk 0)
    #pragma unroll
    for (int e = 0; e < 7; e++) {
        float nb = (e == 0) ? sA[1] : fmaxf(sA[e-1], sA[e+1]);
        float cand = fmaf(0.875f, sA[e], 0.125f * nb);
        if (cand > best) { best = cand; bestE = e; }
    }

    #pragma unroll
    for (int q = 1; q < 6; q++) {
        chunk8(c00, c01, c10, c11, q*8, fw, fh, sB);
        {   // e = 8q-1 (chunk boundary)
            float nb = fmaxf(sA[6], sB[0]);
            float cand = fmaf(0.875f, sA[7], 0.125f * nb);
            if (cand > best) { best = cand; bestE = 8*q - 1; }
        }
        {   // e = 8q
            float nb = fmaxf(sA[7], sB[1]);
            float cand = fmaf(0.875f, sB[0], 0.125f * nb);
            if (cand > best) { best = cand; bestE = 8*q; }
        }
        #pragma unroll
        for (int j = 1; j < 7; j++) {    // e = 8q+1 .. 8q+6
            float nb = fmaxf(sB[j-1], sB[j+1]);
            float cand = fmaf(0.875f, sB[j], 0.125f * nb);
            if (cand > best) { best = cand; bestE = 8*q + j; }
        }
        #pragma unroll
        for (int j = 0; j < 8; j++) sA[j] = sB[j];
    }

    {   // e = 47
        float nb = sA[6];
        float cand = fmaf(0.875f, sA[7], 0.125f * nb);
        if (cand > best) { best = cand; bestE = 47; }
    }
    float s47 = sA[7];

    int k;
    if (s47 > best) {
        k = 4*(ND-1) + 2;                   // 190: exact sample s[47]
    } else if (bestE < 0) {
        k = 0;
    } else {
        float smL = -3.0e38f, smR = -3.0e38f;
        if (bestE > 0)      smL = bilin1(c00, c01, c10, c11, bestE - 1, fw, fh);
        if (bestE < ND - 1) smR = bilin1(c00, c01, c10, c11, bestE + 1, fw, fh);
        k = 4*bestE + 1 + ((smR > smL) ? 1 : 0);   // tie -> left (smaller k)
    }
    k = max(k, 1);
    pred[ho*WOUT + wo] = (float)k;
}

// ---------------------------------------------------------------------------
extern "C" void kernel_launch(void* const* d_in, const int* in_sizes, int n_in,
                              void* d_out, int out_size)
{
    const float* left  = (const float*)d_in[0];
    const float* right = (const float*)d_in[1];
    float* out = (float*)d_out;

    const int smem_bytes = 4 * C * WF * (int)sizeof(float);   // 96 KB
    cudaFuncSetAttribute(cost_kernel,
                         cudaFuncAttributeMaxDynamicSharedMemorySize, smem_bytes);

    dim3 g1(HF/2, 3), b1(768);
    cost_kernel<<<g1, b1, smem_bytes>>>(left, right, out);

    dim3 g2(WOUT/32, HOUT/8), b2(32, 8);
    pred_kernel<<<g2, b2>>>(out, out + COST_ELEMS);
}

// round 5
// speedup vs baseline: 2.3895x; 1.1648x over previous
#include <cuda_runtime.h>

#define C   32
#define HF  96
#define WF  192
#define DD  192
#define HOUT 384
#define WOUT 768
#define ND  48
#define CHW (HF*WF)
#define COST_ELEMS (DD*HF*WF)
#define TP  (WF + 16)          // padded t row: 16 zero floats before index 0

// ---------------------------------------------------------------------------
// Kernel 1: normalized cosine cost volume. ONE WAVE: grid (48 h-pairs, 3),
// 768 threads, ~100KB dynamic smem (1 block/SM, 24 warps). Block loads 2
// h-rows of both feature maps, L2-normalizes per pixel, then each thread
// computes exactly one 4w x 8d register tile with LDS.128 operand loads.
// The t rows are stored with a 16-float zero pad on the left, so operand
// windows that cross w-d=0 load exact zeros vectorized -> ZERO divergence.
// cost[d,h,w] = sum_c rn[c,w]*tn[c,w-d], exactly 0 for w<d.
// blockIdx.y takes d-octs {y, y+3, y+6, ...} (interleave balances triangle).
// ---------------------------------------------------------------------------
__global__ __launch_bounds__(768) void cost_kernel(
    const float* __restrict__ ref, const float* __restrict__ tgt,
    float* __restrict__ out)
{
    extern __shared__ float smbuf[];
    float (*r)[C][WF] = reinterpret_cast<float (*)[C][WF]>(smbuf);
    float (*t)[C][TP] = reinterpret_cast<float (*)[C][TP]>(smbuf + 2*C*WF);

    const int hp  = blockIdx.x;          // h-pair 0..47
    const int by  = blockIdx.y;          // 0..2
    const int tid = threadIdx.x;         // 0..767
    const int hrow0 = hp * 2;

    // zero the 2*C*16 pad floats (= 256 float4)
    if (tid < 2*C*4) {
        int row = tid / (C*4);
        int c   = (tid / 4) % C;
        int q   = tid % 4;
        *reinterpret_cast<float4*>(&t[row][c][q*4]) = make_float4(0.f,0.f,0.f,0.f);
    }

    // vectorized loads: 3072 float4 per tensor (2 rows x 32 c x 48 quads)
    {
        #pragma unroll
        for (int j = 0; j < 4; j++) {
            int k   = tid + j*768;         // 0..3071
            int c   = k / 48;              // 0..63  (row*32 + channel)
            int kk  = k % 48;
            int row = c / C;
            int cc  = c % C;
            *reinterpret_cast<float4*>(&r[row][cc][kk*4]) =
                *reinterpret_cast<const float4*>(ref + cc*CHW + (hrow0+row)*WF + kk*4);
            *reinterpret_cast<float4*>(&t[row][cc][16 + kk*4]) =
                *reinterpret_cast<const float4*>(tgt + cc*CHW + (hrow0+row)*WF + kk*4);
        }
    }
    __syncthreads();

    // per-pixel channel normalization: 384 columns (2 rows x 192 w)
    if (tid < 2*WF) {
        int row = tid / WF;
        int w   = tid % WF;
        float sr = 0.f, st = 0.f;
        #pragma unroll
        for (int c = 0; c < C; c++) {
            float a = r[row][c][w];      sr = fmaf(a, a, sr);
            float b = t[row][c][16 + w]; st = fmaf(b, b, st);
        }
        float ir  = rsqrtf(sr + 1e-12f);
        float itv = rsqrtf(st + 1e-12f);
        #pragma unroll
        for (int c = 0; c < C; c++) { r[row][c][w] *= ir; t[row][c][16 + w] *= itv; }
    }
    __syncthreads();

    // one 4w x 8d tile per thread
    const int hr = (tid >= 384) ? 1 : 0;
    const int tm = tid - hr*384;         // 0..383
    const int wq = tm % 48;
    const int dq = tm / 48;              // 0..7
    const int w0 = wq * 4;
    const int d0 = 8 * (3*dq + by);      // interleaved d-oct
    const int h  = hrow0 + hr;

    float4 acc[8];
    #pragma unroll
    for (int i = 0; i < 8; i++) acc[i] = make_float4(0.f, 0.f, 0.f, 0.f);

    // operand window base in padded coords: pb = 16 + (w0 - d0 - 8), mult of 4
    const int pb = 16 + w0 - d0 - 8;

    if (w0 - d0 >= 0) {   // tile has >=1 valid output (w0 mult4, d0 mult8)
        #pragma unroll
        for (int c = 0; c < C; c++) {
            float4 a  = *reinterpret_cast<const float4*>(&r[hr][c][w0]);
            float4 v0 = *reinterpret_cast<const float4*>(&t[hr][c][pb]);
            float4 v1 = *reinterpret_cast<const float4*>(&t[hr][c][pb + 4]);
            float4 v2 = *reinterpret_cast<const float4*>(&t[hr][c][pb + 8]);
            float e[12] = {v0.x, v0.y, v0.z, v0.w,
                           v1.x, v1.y, v1.z, v1.w,
                           v2.x, v2.y, v2.z, v2.w};
            #pragma unroll
            for (int i = 0; i < 8; i++) {
                acc[i].x = fmaf(a.x, e[8  - i], acc[i].x);  // w=w0,   d=d0+i
                acc[i].y = fmaf(a.y, e[9  - i], acc[i].y);  // w=w0+1
                acc[i].z = fmaf(a.z, e[10 - i], acc[i].z);  // w=w0+2
                acc[i].w = fmaf(a.w, e[11 - i], acc[i].w);  // w=w0+3
            }
        }
    }
    // w0 < d0: entire tile is w < d -> exact zeros

    #pragma unroll
    for (int i = 0; i < 8; i++) {
        *reinterpret_cast<float4*>(&out[((d0 + i)*HF + h)*WF + w0]) = acc[i];
    }
}

// ---------------------------------------------------------------------------
// Kernel 2: fused trilinear upsample (jax half-pixel == clamped lerp) +
// argmax over 192 d-samples + clamp(.,1). Chunked-by-8 vectorized streaming:
// candidate at e = 0.875*s[e] + 0.125*max(s[e-1], s[e+1]); exact edge
// samples s[0] (k=0) and s[47] (k=190). First-occurrence ties preserved
// (ascending e, strict >). smem stride 52: 16B-aligned, conflict-free phases.
// ---------------------------------------------------------------------------
#define SSTR 52

__device__ __forceinline__ float bilin1(const float* __restrict__ c00,
                                        const float* __restrict__ c01,
                                        const float* __restrict__ c10,
                                        const float* __restrict__ c11,
                                        int d, float fw, float fh)
{
    float t0 = fmaf(fw, c01[d] - c00[d], c00[d]);
    float t1 = fmaf(fw, c11[d] - c10[d], c10[d]);
    return fmaf(fh, t1 - t0, t0);
}

__device__ __forceinline__ void chunk8(const float* __restrict__ c00,
                                       const float* __restrict__ c01,
                                       const float* __restrict__ c10,
                                       const float* __restrict__ c11,
                                       int dbase, float fw, float fh,
                                       float* __restrict__ s)
{
    #pragma unroll
    for (int half = 0; half < 2; half++) {
        float4 v00 = *reinterpret_cast<const float4*>(c00 + dbase + half*4);
        float4 v01 = *reinterpret_cast<const float4*>(c01 + dbase + half*4);
        float4 v10 = *reinterpret_cast<const float4*>(c10 + dbase + half*4);
        float4 v11 = *reinterpret_cast<const float4*>(c11 + dbase + half*4);
        float t0, t1;
        t0 = fmaf(fw, v01.x - v00.x, v00.x);
        t1 = fmaf(fw, v11.x - v10.x, v10.x);
        s[half*4+0] = fmaf(fh, t1 - t0, t0);
        t0 = fmaf(fw, v01.y - v00.y, v00.y);
        t1 = fmaf(fw, v11.y - v10.y, v10.y);
        s[half*4+1] = fmaf(fh, t1 - t0, t0);
        t0 = fmaf(fw, v01.z - v00.z, v00.z);
        t1 = fmaf(fw, v11.z - v10.z, v10.z);
        s[half*4+2] = fmaf(fh, t1 - t0, t0);
        t0 = fmaf(fw, v01.w - v00.w, v00.w);
        t1 = fmaf(fw, v11.w - v10.w, v10.w);
        s[half*4+3] = fmaf(fh, t1 - t0, t0);
    }
}

__global__ __launch_bounds__(256) void pred_kernel(
    const float* __restrict__ cost, float* __restrict__ pred)
{
    __shared__ float sc[4][10][SSTR];  // [h-row][w-col][d], padded stride
    const int tx = threadIdx.x, ty = threadIdx.y;
    const int tid = ty*32 + tx;
    const int hb = 2*(int)blockIdx.y - 1;
    const int wb = 8*(int)blockIdx.x - 1;

    #pragma unroll
    for (int it = 0; it < 8; it++) {
        int i = tid + it * 256;
        if (i < 4*10*ND) {
            int wc = i % 10;
            int hr = (i / 10) % 4;
            int d  = i / 40;
            int hh = min(max(hb + hr, 0), HF - 1);
            int ww = min(max(wb + wc, 0), WF - 1);
            sc[hr][wc][d] = cost[(d*HF + hh)*WF + ww];
        }
    }
    __syncthreads();

    const int wo = blockIdx.x*32 + tx;
    const int ho = blockIdx.y*8 + ty;

    float xh = fminf(fmaxf(0.25f*(float)ho - 0.375f, 0.f), (float)(HF - 1));
    int   h0 = min((int)xh, HF - 2);
    float fh = xh - (float)h0;
    float xw = fminf(fmaxf(0.25f*(float)wo - 0.375f, 0.f), (float)(WF - 1));
    int   w0 = min((int)xw, WF - 2);
    float fw = xw - (float)w0;

    const int lh = h0 - hb;
    const int lw = w0 - wb;
    const float* c00 = &sc[lh][lw][0];
    const float* c01 = &sc[lh][lw+1][0];
    const float* c10 = &sc[lh+1][lw][0];
    const float* c11 = &sc[lh+1][lw+1][0];

    float sA[8], sB[8];
    chunk8(c00, c01, c10, c11, 0, fw, fh, sA);

    float best = sA[0];                  // exact sample s[0] at k = 0
    int bestE = -1;                      // -1 => k = 0

    // e = 0..6 (within chunk 0)
    #pragma unroll
    for (int e = 0; e < 7; e++) {
        float nb = (e == 0) ? sA[1] : fmaxf(sA[e-1], sA[e+1]);
        float cand = fmaf(0.875f, sA[e], 0.125f * nb);
        if (cand > best) { best = cand; bestE = e; }
    }

    #pragma unroll
    for (int q = 1; q < 6; q++) {
        chunk8(c00, c01, c10, c11, q*8, fw, fh, sB);
        {   // e = 8q-1 (chunk boundary)
            float nb = fmaxf(sA[6], sB[0]);
            float cand = fmaf(0.875f, sA[7], 0.125f * nb);
            if (cand > best) { best = cand; bestE = 8*q - 1; }
        }
        {   // e = 8q
            float nb = fmaxf(sA[7], sB[1]);
            float cand = fmaf(0.875f, sB[0], 0.125f * nb);
            if (cand > best) { best = cand; bestE = 8*q; }
        }
        #pragma unroll
        for (int j = 1; j < 7; j++) {    // e = 8q+1 .. 8q+6
            float nb = fmaxf(sB[j-1], sB[j+1]);
            float cand = fmaf(0.875f, sB[j], 0.125f * nb);
            if (cand > best) { best = cand; bestE = 8*q + j; }
        }
        #pragma unroll
        for (int j = 0; j < 8; j++) sA[j] = sB[j];
    }

    {   // e = 47
        float nb = sA[6];
        float cand = fmaf(0.875f, sA[7], 0.125f * nb);
        if (cand > best) { best = cand; bestE = 47; }
    }
    float s47 = sA[7];

    int k;
    if (s47 > best) {
        k = 4*(ND-1) + 2;                   // 190: exact sample s[47]
    } else if (bestE < 0) {
        k = 0;
    } else {
        float smL = -3.0e38f, smR = -3.0e38f;
        if (bestE > 0)      smL = bilin1(c00, c01, c10, c11, bestE - 1, fw, fh);
        if (bestE < ND - 1) smR = bilin1(c00, c01, c10, c11, bestE + 1, fw, fh);
        k = 4*bestE + 1 + ((smR > smL) ? 1 : 0);   // tie -> left (smaller k)
    }
    k = max(k, 1);
    pred[ho*WOUT + wo] = (float)k;
}

// ---------------------------------------------------------------------------
extern "C" void kernel_launch(void* const* d_in, const int* in_sizes, int n_in,
                              void* d_out, int out_size)
{
    const float* left  = (const float*)d_in[0];
    const float* right = (const float*)d_in[1];
    float* out = (float*)d_out;

    const int smem_bytes = (2*C*WF + 2*C*TP) * (int)sizeof(float);  // 100 KB
    cudaFuncSetAttribute(cost_kernel,
                         cudaFuncAttributeMaxDynamicSharedMemorySize, smem_bytes);

    dim3 g1(HF/2, 3), b1(768);
    cost_kernel<<<g1, b1, smem_bytes>>>(left, right, out);

    dim3 g2(WOUT/32, HOUT/8), b2(32, 8);
    pred_kernel<<<g2, b2>>>(out, out + COST_ELEMS);
}